// round 10
// baseline (speedup 1.0000x reference)
#include <cuda_runtime.h>
#include <cstdint>

// Quantizer — VQ assignment via mma.sync tf32 3-term split (sm_100-safe PTX).
//   x [B,H,L,D] f32, c_sum [H,S,D] f32, c_count [H,S] f32
//   out = [delta_onehot [B,H,L,S] f32 | c [H,S,D] f32]
// score_s = |c_s|^2 + x.(-2 c_s); 3-term tf32 split, fp32 accumulate
// (residual ~1e-5 << argmin gaps; rel_err measured 0.0 R7-R9).
// R9 -> R10: fragment layout v2 (contiguous per-lane fragments -> LDS.128,
// halves LDS count), 4-slot B ring reusing dead A smem (barriers 16 -> 9,
// cp.async waits ~free). Tensor was 67.6% with L1 47.3% / alu 18.1%.

#define Bq 4
#define Hq 16
#define Lq 4096
#define Dq 64
#define Sq 512
#define ONEHOT_ELEMS ((size_t)Bq * Hq * Lq * Sq)

// Codebook scratch: per (h,s) row of 128 floats: [-2c hi (64) | -2c lo (64)],
// layout v2: pos(k) = m*16 + kb*2 + j, where k = kb*8 + j*4 + m.
__device__ float g_cbB[Hq * Sq * 128];   // 4 MB
__device__ float g_c2[Hq * Sq];          // 32 KB

// -------------------- helpers --------------------
__device__ __forceinline__ uint32_t smem_u32(const void* p) {
    uint32_t a;
    asm("{ .reg .u64 t; cvta.to.shared.u64 t, %1; cvt.u32.u64 %0, t; }"
        : "=r"(a) : "l"(p));
    return a;
}
__device__ __forceinline__ float to_tf32(float x) {
    uint32_t u;
    asm("cvt.rna.tf32.f32 %0, %1;" : "=r"(u) : "f"(x));
    return __uint_as_float(u);
}
__device__ __forceinline__ void cp16(uint32_t s, const void* g) {
    asm volatile("cp.async.ca.shared.global [%0], [%1], 16;" :: "r"(s), "l"(g));
}
#define CP_COMMIT() asm volatile("cp.async.commit_group;" ::: "memory")
#define CP_WAIT0()  asm volatile("cp.async.wait_group 0;" ::: "memory")

// m16n8k8 tf32 row.col; operand mapping verified R6-R9 (rel_err 0.0).
__device__ __forceinline__ void mma1688(float4& d, float2 a0, float2 a1, float2 b) {
    asm("mma.sync.aligned.m16n8k8.row.col.f32.tf32.tf32.f32 "
        "{%0,%1,%2,%3}, {%4,%5,%6,%7}, {%8,%9}, {%0,%1,%2,%3};"
        : "+f"(d.x), "+f"(d.y), "+f"(d.z), "+f"(d.w)
        : "r"(__float_as_uint(a0.x)), "r"(__float_as_uint(a1.x)),
          "r"(__float_as_uint(a0.y)), "r"(__float_as_uint(a1.y)),
          "r"(__float_as_uint(b.x)),  "r"(__float_as_uint(b.y)));
}

// layout v2 position of k within a 64-float half-row.
__device__ __forceinline__ int kpos2(int k) {
    int kb = k >> 3, r = k & 7, mm = r & 3, j = (r >> 2) & 1;
    return mm * 16 + kb * 2 + j;
}

// -------------------- prep --------------------
__global__ void prep_kernel(const float* __restrict__ c_sum,
                            const float* __restrict__ c_count,
                            float* __restrict__ out_c) {
    const int cw = blockIdx.x;        // h*S + s
    const int lane = threadIdx.x;     // 2 dims per lane
    float cnt = fmaxf(c_count[cw], 1e-6f);

    float2 v = ((const float2*)(c_sum + (size_t)cw * Dq))[lane];
    float a = v.x / cnt;              // IEEE divide: matches reference
    float b = v.y / cnt;
    ((float2*)(out_c + (size_t)cw * Dq))[lane] = make_float2(a, b);

    float* row = g_cbB + (size_t)cw * 128;
    int k0 = 2 * lane, k1 = 2 * lane + 1;
    float m0 = -2.0f * a, m1 = -2.0f * b;
    float h0 = to_tf32(m0), h1 = to_tf32(m1);
    row[kpos2(k0)]      = h0;
    row[kpos2(k1)]      = h1;
    row[64 + kpos2(k0)] = to_tf32(m0 - h0);
    row[64 + kpos2(k1)] = to_tf32(m1 - h1);

    float sq = a * a + b * b;
    #pragma unroll
    for (int o = 16; o > 0; o >>= 1) sq += __shfl_xor_sync(0xFFFFFFFFu, sq, o);
    if (lane == 0) g_c2[cw] = sq;
}

// -------------------- main --------------------
// CTA: 128 threads (4 warps), 128 rows, 2 CTAs/SM. Warp tile M=32, A hi/lo in
// registers. B streamed in 32-codeword chunks through a 4-slot smem ring
// (slots 2,3 live in the A region, which is dead after the prologue).
#define ROWS 128
#define NTHR 128
#define CH   32
#define RSTRIDE 132                   // (r*33+..)%8 uniform for LDS.128
#define SLOT_F  (CH * RSTRIDE)        // 4224 floats per ring slot
#define AREG_F  (ROWS * RSTRIDE)      // 16896 (holds slots 2,3 + slack)
#define B0_F    AREG_F                // 16896
#define B1_F    (B0_F + SLOT_F)       // 21120
#define C2_F    (B1_F + SLOT_F)       // 25344
#define IDX_F   (C2_F + Sq)           // 25856
#define SMEM_TOTAL ((IDX_F + ROWS) * 4)   // 103936 B -> 2 CTAs/SM

__global__ __launch_bounds__(NTHR, 2)
void vq_kernel(const float* __restrict__ x, float* __restrict__ out) {
    extern __shared__ float sm[];
    const uint32_t sb = smem_u32(sm);
    const int tid = threadIdx.x;
    const int wid = tid >> 5, lane = tid & 31;
    const int g = lane >> 2, m = lane & 3;
    const int wb = wid * 32;

    const int rowbase = blockIdx.x * ROWS;
    const int h = (blockIdx.x >> 5) & (Hq - 1);   // 32 CTAs per (b,h)
    const char* cb_bytes = (const char*)(g_cbB + (size_t)h * Sq * 128);

    // Ring slot base offsets (floats): chunk n -> slot n&3.
    const uint32_t slot_f[4] = {B0_F, B1_F, 0u, SLOT_F};

    // Hoisted cp.async addressing: 8 x 16B per thread per chunk.
    uint32_t cp_dst[8], cp_src[8];
    #pragma unroll
    for (int j = 0; j < 8; ++j) {
        int i = j * NTHR + tid;           // 0..1023 (16B units)
        int r = i >> 5, q = i & 31;
        cp_dst[j] = (uint32_t)((r * RSTRIDE + q * 4) * 4);
        cp_src[j] = (uint32_t)(i * 16);
    }

    // Prologue copies: chunks 0,1 -> slots 0,1 (disjoint from A region).
    #pragma unroll
    for (int j = 0; j < 8; ++j)
        cp16(sb + B0_F * 4 + cp_dst[j], cb_bytes + cp_src[j]);
    CP_COMMIT();
    #pragma unroll
    for (int j = 0; j < 8; ++j)
        cp16(sb + B1_F * 4 + cp_dst[j], cb_bytes + 16384 + cp_src[j]);
    CP_COMMIT();

    // Stage c2 + A tile (layout v2, one thread per row).
    for (int i = tid; i < Sq; i += NTHR) sm[C2_F + i] = g_c2[h * Sq + i];
    {
        const float4* xr = (const float4*)(x + (size_t)(rowbase + tid) * Dq);
        float4 v[16];
        #pragma unroll
        for (int i = 0; i < 16; ++i) v[i] = xr[i];
        const float* vf = (const float*)v;
        float* dst = sm + tid * RSTRIDE;
        #pragma unroll
        for (int mm = 0; mm < 4; ++mm) {
            #pragma unroll
            for (int kp = 0; kp < 4; ++kp) {
                // float4 at pos mm*16+4kp covers (kb=2kp, j0/j1), (kb=2kp+1, j0/j1)
                float a0 = vf[16 * kp + mm];          // k = 16kp+mm
                float a1 = vf[16 * kp + mm + 4];
                float a2 = vf[16 * kp + 8 + mm];
                float a3 = vf[16 * kp + 8 + mm + 4];
                float h0 = to_tf32(a0), h1 = to_tf32(a1),
                      h2 = to_tf32(a2), h3 = to_tf32(a3);
                *(float4*)(dst + mm * 16 + kp * 4) =
                    make_float4(h0, h1, h2, h3);
                *(float4*)(dst + 64 + mm * 16 + kp * 4) =
                    make_float4(to_tf32(a0 - h0), to_tf32(a1 - h1),
                                to_tf32(a2 - h2), to_tf32(a3 - h3));
            }
        }
    }
    __syncthreads();

    // A fragments to registers (LDS.128): [tile][kb][row-half], hi and lo.
    float2 Ah[2][8][2], Al[2][8][2];
    #pragma unroll
    for (int t = 0; t < 2; ++t) {
        const float* p0 = sm + (wb + t * 16 + g) * RSTRIDE + m * 16;
        const float* p8 = p0 + 8 * RSTRIDE;
        #pragma unroll
        for (int kp = 0; kp < 4; ++kp) {
            float4 h0 = *(const float4*)(p0 + kp * 4);
            float4 h8 = *(const float4*)(p8 + kp * 4);
            float4 q0 = *(const float4*)(p0 + 64 + kp * 4);
            float4 q8 = *(const float4*)(p8 + 64 + kp * 4);
            Ah[t][2*kp][0]   = make_float2(h0.x, h0.y);
            Ah[t][2*kp+1][0] = make_float2(h0.z, h0.w);
            Ah[t][2*kp][1]   = make_float2(h8.x, h8.y);
            Ah[t][2*kp+1][1] = make_float2(h8.z, h8.w);
            Al[t][2*kp][0]   = make_float2(q0.x, q0.y);
            Al[t][2*kp+1][0] = make_float2(q0.z, q0.w);
            Al[t][2*kp][1]   = make_float2(q8.x, q8.y);
            Al[t][2*kp+1][1] = make_float2(q8.z, q8.w);
        }
    }

    float best[4] = {3.0e38f, 3.0e38f, 3.0e38f, 3.0e38f};
    int bidx[4] = {0, 0, 0, 0};

    // Windows of 2 chunks; one barrier per window; commits post-barrier so a
    // slot is never overwritten while a lagging warp still reads it.
    for (int p = 0; p < 16; p += 2) {
        CP_WAIT0();            // own copies of chunks p, p+1 (2 chunks old)
        __syncthreads();       // cross-warp visibility + slot-reuse safety
        if (p + 2 < 16) {
            uint32_t d0 = sb + slot_f[(p + 2) & 3] * 4;
            const char* s0 = cb_bytes + (size_t)(p + 2) * 16384;
            #pragma unroll
            for (int j = 0; j < 8; ++j) cp16(d0 + cp_dst[j], s0 + cp_src[j]);
            CP_COMMIT();
            uint32_t d1 = sb + slot_f[(p + 3) & 3] * 4;
            const char* s1 = cb_bytes + (size_t)(p + 3) * 16384;
            #pragma unroll
            for (int j = 0; j < 8; ++j) cp16(d1 + cp_dst[j], s1 + cp_src[j]);
            CP_COMMIT();
        }

        #pragma unroll
        for (int q2 = 0; q2 < 2; ++q2) {
            const int nch = p + q2;
            const float* Bbuf = sm + slot_f[nch & 3];

            float4 acc[4][2];             // [colblock][tile] -> 8 chains
            #pragma unroll
            for (int cb = 0; cb < 4; ++cb) {
                float2 cv = *(const float2*)(sm + C2_F + nch * CH + cb * 8 + m * 2);
                #pragma unroll
                for (int t = 0; t < 2; ++t)
                    acc[cb][t] = make_float4(cv.x, cv.y, cv.x, cv.y);
            }

            const float* bn0 = Bbuf + g * RSTRIDE + m * 16;
            const float* bn1 = bn0 + 8 * RSTRIDE;
            const float* bn2 = bn0 + 16 * RSTRIDE;
            const float* bn3 = bn0 + 24 * RSTRIDE;
            #pragma unroll
            for (int kp = 0; kp < 4; ++kp) {
                float4 H0 = *(const float4*)(bn0 + kp * 4);
                float4 H1 = *(const float4*)(bn1 + kp * 4);
                float4 H2 = *(const float4*)(bn2 + kp * 4);
                float4 H3 = *(const float4*)(bn3 + kp * 4);
                float4 L0 = *(const float4*)(bn0 + 64 + kp * 4);
                float4 L1 = *(const float4*)(bn1 + 64 + kp * 4);
                float4 L2 = *(const float4*)(bn2 + 64 + kp * 4);
                float4 L3 = *(const float4*)(bn3 + 64 + kp * 4);
                #pragma unroll
                for (int kk = 0; kk < 2; ++kk) {     // kb = 2kp + kk
                    const int kb = 2 * kp + kk;
                    float2 bh0 = kk ? make_float2(H0.z, H0.w) : make_float2(H0.x, H0.y);
                    float2 bh1 = kk ? make_float2(H1.z, H1.w) : make_float2(H1.x, H1.y);
                    float2 bh2 = kk ? make_float2(H2.z, H2.w) : make_float2(H2.x, H2.y);
                    float2 bh3 = kk ? make_float2(H3.z, H3.w) : make_float2(H3.x, H3.y);
                    float2 bl0 = kk ? make_float2(L0.z, L0.w) : make_float2(L0.x, L0.y);
                    float2 bl1 = kk ? make_float2(L1.z, L1.w) : make_float2(L1.x, L1.y);
                    float2 bl2 = kk ? make_float2(L2.z, L2.w) : make_float2(L2.x, L2.y);
                    float2 bl3 = kk ? make_float2(L3.z, L3.w) : make_float2(L3.x, L3.y);
                    // hi*hi
                    mma1688(acc[0][0], Ah[0][kb][0], Ah[0][kb][1], bh0);
                    mma1688(acc[0][1], Ah[1][kb][0], Ah[1][kb][1], bh0);
                    mma1688(acc[1][0], Ah[0][kb][0], Ah[0][kb][1], bh1);
                    mma1688(acc[1][1], Ah[1][kb][0], Ah[1][kb][1], bh1);
                    mma1688(acc[2][0], Ah[0][kb][0], Ah[0][kb][1], bh2);
                    mma1688(acc[2][1], Ah[1][kb][0], Ah[1][kb][1], bh2);
                    mma1688(acc[3][0], Ah[0][kb][0], Ah[0][kb][1], bh3);
                    mma1688(acc[3][1], Ah[1][kb][0], Ah[1][kb][1], bh3);
                    // lo*hi
                    mma1688(acc[0][0], Al[0][kb][0], Al[0][kb][1], bh0);
                    mma1688(acc[0][1], Al[1][kb][0], Al[1][kb][1], bh0);
                    mma1688(acc[1][0], Al[0][kb][0], Al[0][kb][1], bh1);
                    mma1688(acc[1][1], Al[1][kb][0], Al[1][kb][1], bh1);
                    mma1688(acc[2][0], Al[0][kb][0], Al[0][kb][1], bh2);
                    mma1688(acc[2][1], Al[1][kb][0], Al[1][kb][1], bh2);
                    mma1688(acc[3][0], Al[0][kb][0], Al[0][kb][1], bh3);
                    mma1688(acc[3][1], Al[1][kb][0], Al[1][kb][1], bh3);
                    // hi*lo
                    mma1688(acc[0][0], Ah[0][kb][0], Ah[0][kb][1], bl0);
                    mma1688(acc[0][1], Ah[1][kb][0], Ah[1][kb][1], bl0);
                    mma1688(acc[1][0], Ah[0][kb][0], Ah[0][kb][1], bl1);
                    mma1688(acc[1][1], Ah[1][kb][0], Ah[1][kb][1], bl1);
                    mma1688(acc[2][0], Ah[0][kb][0], Ah[0][kb][1], bl2);
                    mma1688(acc[2][1], Ah[1][kb][0], Ah[1][kb][1], bl2);
                    mma1688(acc[3][0], Ah[0][kb][0], Ah[0][kb][1], bl3);
                    mma1688(acc[3][1], Ah[1][kb][0], Ah[1][kb][1], bl3);
                }
            }

            // Argmin update (ascending n, strict '<' = first-min, jnp.argmin).
            #pragma unroll
            for (int cb = 0; cb < 4; ++cb) {
                int n0 = nch * CH + cb * 8 + m * 2;
                #pragma unroll
                for (int t = 0; t < 2; ++t) {
                    int s0 = t * 2, s1 = t * 2 + 1;   // rows g, g+8 (per tile)
                    float4 a = acc[cb][t];
                    if (a.x < best[s0]) { best[s0] = a.x; bidx[s0] = n0; }
                    if (a.y < best[s0]) { best[s0] = a.y; bidx[s0] = n0 + 1; }
                    if (a.z < best[s1]) { best[s1] = a.z; bidx[s1] = n0; }
                    if (a.w < best[s1]) { best[s1] = a.w; bidx[s1] = n0 + 1; }
                }
            }
        }
    }

    // Reduce across the 4 lanes (m) sharing each row; tie -> smaller index.
    #pragma unroll
    for (int s = 0; s < 4; ++s) {
        #pragma unroll
        for (int o = 1; o <= 2; o <<= 1) {
            float ob = __shfl_xor_sync(0xFFFFFFFFu, best[s], o);
            int   oi = __shfl_xor_sync(0xFFFFFFFFu, bidx[s], o);
            if (ob < best[s] || (ob == best[s] && oi < bidx[s])) {
                best[s] = ob; bidx[s] = oi;
            }
        }
    }
    if (m == 0) {
        int* si = (int*)(sm + IDX_F);
        si[wb + g]          = bidx[0];
        si[wb + g + 8]      = bidx[1];
        si[wb + 16 + g]     = bidx[2];
        si[wb + 16 + g + 8] = bidx[3];
    }
    __syncthreads();

    // Cooperative one-hot: 128 rows x 128 quads, coalesced STG.128.
    const int* si = (const int*)(sm + IDX_F);
    float4* ob4 = (float4*)(out + (size_t)rowbase * Sq);
    #pragma unroll 4
    for (int it = 0; it < 128; ++it) {
        int idx = it * NTHR + tid;
        int r = idx >> 7, c4 = idx & 127;
        int b = si[r];
        int base = c4 << 2;
        float4 v;
        v.x = (b == base)     ? 1.0f : 0.0f;
        v.y = (b == base + 1) ? 1.0f : 0.0f;
        v.z = (b == base + 2) ? 1.0f : 0.0f;
        v.w = (b == base + 3) ? 1.0f : 0.0f;
        ob4[idx] = v;
    }
}

// ---------------------------------------------------------------------------
extern "C" void kernel_launch(void* const* d_in, const int* in_sizes, int n_in,
                              void* d_out, int out_size) {
    const float* x       = (const float*)d_in[0];
    const float* c_sum   = (const float*)d_in[1];
    const float* c_count = (const float*)d_in[2];
    float* out   = (float*)d_out;
    float* out_c = out + ONEHOT_ELEMS;

    (void)in_sizes; (void)n_in; (void)out_size;

    cudaFuncSetAttribute(vq_kernel,
                         cudaFuncAttributeMaxDynamicSharedMemorySize,
                         SMEM_TOTAL);

    prep_kernel<<<Hq * Sq, 32>>>(c_sum, c_count, out_c);
    vq_kernel<<<(Bq * Hq * Lq) / ROWS, NTHR, SMEM_TOTAL>>>(x, out);
}

// round 11
// speedup vs baseline: 1.0497x; 1.0497x over previous
#include <cuda_runtime.h>
#include <cstdint>

// Quantizer — VQ assignment via mma.sync tf32 3-term split (sm_100-safe PTX).
//   x [B,H,L,D] f32, c_sum [H,S,D] f32, c_count [H,S] f32
//   out = [delta_onehot [B,H,L,S] f32 | c [H,S,D] f32]
// score_s = |c_s|^2 + x.(-2 c_s); 3-term tf32 split, fp32 accumulate
// (residual ~1e-5 << argmin gaps; rel_err measured 0.0 R7-R10).
// R10 post-mortem: layout v2 + full window unroll -> 255 regs (spills),
// L1 61%, tensor 55%. R11 = exact R9 base + ONLY the 4-slot B ring
// (barriers 16 -> 9, slots 2,3 in the dead A-staging region), inner
// 2-chunk loop kept rolled to hold register pressure at R9 levels.

#define Bq 4
#define Hq 16
#define Lq 4096
#define Dq 64
#define Sq 512
#define ONEHOT_ELEMS ((size_t)Bq * Hq * Lq * Sq)

// Codebook scratch: per (h,s) row of 128 floats: [-2c hi (64) | -2c lo (64)],
// k-permuted so mma B-fragment pairs (k, k+4) are adjacent (one LDS.64).
__device__ float g_cbB[Hq * Sq * 128];   // 4 MB
__device__ float g_c2[Hq * Sq];          // 32 KB

// -------------------- helpers --------------------
__device__ __forceinline__ uint32_t smem_u32(const void* p) {
    uint32_t a;
    asm("{ .reg .u64 t; cvta.to.shared.u64 t, %1; cvt.u32.u64 %0, t; }"
        : "=r"(a) : "l"(p));
    return a;
}
__device__ __forceinline__ float to_tf32(float x) {
    uint32_t u;
    asm("cvt.rna.tf32.f32 %0, %1;" : "=r"(u) : "f"(x));
    return __uint_as_float(u);
}
__device__ __forceinline__ void cp16(uint32_t s, const void* g) {
    asm volatile("cp.async.ca.shared.global [%0], [%1], 16;" :: "r"(s), "l"(g));
}
#define CP_COMMIT() asm volatile("cp.async.commit_group;" ::: "memory")
#define CP_WAIT0()  asm volatile("cp.async.wait_group 0;" ::: "memory")

// m16n8k8 tf32 row.col; operand mapping verified R6-R10 (rel_err 0.0).
__device__ __forceinline__ void mma1688(float4& d, float2 a0, float2 a1, float2 b) {
    asm("mma.sync.aligned.m16n8k8.row.col.f32.tf32.tf32.f32 "
        "{%0,%1,%2,%3}, {%4,%5,%6,%7}, {%8,%9}, {%0,%1,%2,%3};"
        : "+f"(d.x), "+f"(d.y), "+f"(d.z), "+f"(d.w)
        : "r"(__float_as_uint(a0.x)), "r"(__float_as_uint(a1.x)),
          "r"(__float_as_uint(a0.y)), "r"(__float_as_uint(a1.y)),
          "r"(__float_as_uint(b.x)),  "r"(__float_as_uint(b.y)));
}

// k-permutation: pos(k) puts (m, m+4) adjacent within each 8-block.
__device__ __forceinline__ int kpos(int k) {
    return (k & ~7) + ((k & 3) << 1) + ((k >> 2) & 1);
}

// -------------------- prep --------------------
__global__ void prep_kernel(const float* __restrict__ c_sum,
                            const float* __restrict__ c_count,
                            float* __restrict__ out_c) {
    const int cw = blockIdx.x;        // h*S + s
    const int lane = threadIdx.x;     // 2 dims per lane
    float cnt = fmaxf(c_count[cw], 1e-6f);

    float2 v = ((const float2*)(c_sum + (size_t)cw * Dq))[lane];
    float a = v.x / cnt;              // IEEE divide: matches reference
    float b = v.y / cnt;
    ((float2*)(out_c + (size_t)cw * Dq))[lane] = make_float2(a, b);

    float* row = g_cbB + (size_t)cw * 128;
    int k0 = 2 * lane, k1 = 2 * lane + 1;
    float m0 = -2.0f * a, m1 = -2.0f * b;
    float h0 = to_tf32(m0), h1 = to_tf32(m1);
    row[kpos(k0)]      = h0;
    row[kpos(k1)]      = h1;
    row[64 + kpos(k0)] = to_tf32(m0 - h0);
    row[64 + kpos(k1)] = to_tf32(m1 - h1);

    float sq = a * a + b * b;
    #pragma unroll
    for (int o = 16; o > 0; o >>= 1) sq += __shfl_xor_sync(0xFFFFFFFFu, sq, o);
    if (lane == 0) g_c2[cw] = sq;
}

// -------------------- main --------------------
// CTA: 128 threads (4 warps), 128 rows, 2 CTAs/SM. Warp tile M=32, A hi/lo in
// registers. B streamed in 32-codeword chunks through a 4-slot smem ring;
// slots 2,3 live in the A-staging region (dead after the prologue).
#define ROWS 128
#define NTHR 128
#define CH   32
#define RSTRIDE 136                   // padded row (floats)
#define SLOT_F  (CH * RSTRIDE)        // 4352 floats per ring slot
#define AREG_F  (ROWS * RSTRIDE)      // 17408 (holds slots 2,3 + slack)
#define B0_F    AREG_F                // 17408
#define B1_F    (B0_F + SLOT_F)       // 21760
#define C2_F    (B1_F + SLOT_F)       // 26112
#define IDX_F   (C2_F + Sq)           // 26624
#define SMEM_TOTAL ((IDX_F + ROWS) * 4)   // 107008 B -> 2 CTAs/SM

__global__ __launch_bounds__(NTHR, 2)
void vq_kernel(const float* __restrict__ x, float* __restrict__ out) {
    extern __shared__ float sm[];
    const uint32_t sb = smem_u32(sm);
    const int tid = threadIdx.x;
    const int wid = tid >> 5, lane = tid & 31;
    const int g = lane >> 2, m = lane & 3;
    const int wb = wid * 32;

    const int rowbase = blockIdx.x * ROWS;
    const int h = (blockIdx.x >> 5) & (Hq - 1);   // 32 CTAs per (b,h)
    const char* cb_bytes = (const char*)(g_cbB + (size_t)h * Sq * 128);

    // Ring slot base offsets (floats): chunk n -> slot n&3.
    const uint32_t slot_f[4] = {B0_F, B1_F, 0u, SLOT_F};

    // Hoisted cp.async addressing: this thread copies 8 x 16B per chunk.
    uint32_t cp_dst[8];
    uint32_t cp_src[8];
    #pragma unroll
    for (int j = 0; j < 8; ++j) {
        int i = j * NTHR + tid;           // 0..1023 (16B units)
        int r = i >> 5, q = i & 31;
        cp_dst[j] = (uint32_t)((r * RSTRIDE + q * 4) * 4);  // byte off in buf
        cp_src[j] = (uint32_t)(i * 16);                     // byte off in chunk
    }

    // Prologue: prefetch chunks 0,1 into slots 0,1 (outside the A region,
    // so they overlap the A staging below).
    #pragma unroll
    for (int j = 0; j < 8; ++j)
        cp16(sb + B0_F * 4 + cp_dst[j], cb_bytes + cp_src[j]);
    CP_COMMIT();
    #pragma unroll
    for (int j = 0; j < 8; ++j)
        cp16(sb + B1_F * 4 + cp_dst[j], cb_bytes + 16384 + cp_src[j]);
    CP_COMMIT();

    // Stage c2 + A tile (hi/lo tf32, k-permuted, padded rows).
    for (int i = tid; i < Sq; i += NTHR) sm[C2_F + i] = g_c2[h * Sq + i];
    {
        const float4* xb = (const float4*)(x + (size_t)rowbase * Dq);
        #pragma unroll
        for (int it = 0; it < 8; ++it) {
            int i = it * NTHR + tid;          // 128 rows x 8 kblocks
            int r = i >> 3, kb = i & 7;
            float4 v0 = xb[r * 16 + kb * 2];
            float4 v1 = xb[r * 16 + kb * 2 + 1];
            float h0 = to_tf32(v0.x), h1 = to_tf32(v0.y),
                  h2 = to_tf32(v0.z), h3 = to_tf32(v0.w),
                  h4 = to_tf32(v1.x), h5 = to_tf32(v1.y),
                  h6 = to_tf32(v1.z), h7 = to_tf32(v1.w);
            float l0 = to_tf32(v0.x - h0), l1 = to_tf32(v0.y - h1),
                  l2 = to_tf32(v0.z - h2), l3 = to_tf32(v0.w - h3),
                  l4 = to_tf32(v1.x - h4), l5 = to_tf32(v1.y - h5),
                  l6 = to_tf32(v1.z - h6), l7 = to_tf32(v1.w - h7);
            float* dh = sm + r * RSTRIDE + kb * 8;
            // permuted order within 8-block: {k0,k4,k1,k5},{k2,k6,k3,k7}
            ((float4*)dh)[0] = make_float4(h0, h4, h1, h5);
            ((float4*)dh)[1] = make_float4(h2, h6, h3, h7);
            float* dl = dh + 64;
            ((float4*)dl)[0] = make_float4(l0, l4, l1, l5);
            ((float4*)dl)[1] = make_float4(l2, l6, l3, l7);
        }
    }
    __syncthreads();

    // A fragments to registers: [tile][kblock][row-half], hi and lo.
    float2 Ah[2][8][2], Al[2][8][2];
    #pragma unroll
    for (int t = 0; t < 2; ++t)
        #pragma unroll
        for (int kb = 0; kb < 8; ++kb) {
            int r0 = wb + t * 16 + g;
            const float* b0 = sm + r0 * RSTRIDE + kb * 8 + m * 2;
            const float* b8 = b0 + 8 * RSTRIDE;
            Ah[t][kb][0] = *(const float2*)b0;
            Ah[t][kb][1] = *(const float2*)b8;
            Al[t][kb][0] = *(const float2*)(b0 + 64);
            Al[t][kb][1] = *(const float2*)(b8 + 64);
        }
    __syncthreads();   // A-region reads done before ring slots 2,3 overwrite it

    float best[4] = {3.0e38f, 3.0e38f, 3.0e38f, 3.0e38f};
    int bidx[4] = {0, 0, 0, 0};

    // Windows of 2 chunks; one wait+barrier per window. Copies for chunks
    // p+2, p+3 are issued after the barrier, overwriting slots of chunks
    // p-2, p-1 which all warps finished before that barrier.
    for (int p = 0; p < Sq / CH; p += 2) {
        CP_WAIT0();
        __syncthreads();
        if (p + 2 < Sq / CH) {
            uint32_t d0 = sb + slot_f[(p + 2) & 3] * 4;
            const char* s0 = cb_bytes + (size_t)(p + 2) * 16384;
            #pragma unroll
            for (int j = 0; j < 8; ++j) cp16(d0 + cp_dst[j], s0 + cp_src[j]);
            CP_COMMIT();
            uint32_t d1 = sb + slot_f[(p + 3) & 3] * 4;
            const char* s1 = cb_bytes + (size_t)(p + 3) * 16384;
            #pragma unroll
            for (int j = 0; j < 8; ++j) cp16(d1 + cp_dst[j], s1 + cp_src[j]);
            CP_COMMIT();
        }

        #pragma unroll 1
        for (int q2 = 0; q2 < 2; ++q2) {
            const int nch = p + q2;
            const float* Bbuf = sm + slot_f[nch & 3];

            float4 acc[4][2];                 // [colblock][tile] -> 8 chains
            #pragma unroll
            for (int cb = 0; cb < 4; ++cb) {
                float2 cv = *(const float2*)(sm + C2_F + nch * CH + cb * 8 + m * 2);
                #pragma unroll
                for (int t = 0; t < 2; ++t)
                    acc[cb][t] = make_float4(cv.x, cv.y, cv.x, cv.y);
            }

            // kb outermost; per kb load 8 B fragments, 24 MMAs round-robin
            // across the 8 accumulator chains (same-chain spacing = 8).
            const float* bn0 = Bbuf + g * RSTRIDE + m * 2;
            const float* bn1 = bn0 + 8 * RSTRIDE;
            const float* bn2 = bn0 + 16 * RSTRIDE;
            const float* bn3 = bn0 + 24 * RSTRIDE;
            #pragma unroll
            for (int kb = 0; kb < 8; ++kb) {
                float2 bh0 = *(const float2*)(bn0 + kb * 8);
                float2 bh1 = *(const float2*)(bn1 + kb * 8);
                float2 bh2 = *(const float2*)(bn2 + kb * 8);
                float2 bh3 = *(const float2*)(bn3 + kb * 8);
                float2 bl0 = *(const float2*)(bn0 + 64 + kb * 8);
                float2 bl1 = *(const float2*)(bn1 + 64 + kb * 8);
                float2 bl2 = *(const float2*)(bn2 + 64 + kb * 8);
                float2 bl3 = *(const float2*)(bn3 + 64 + kb * 8);
                // term hi*hi
                mma1688(acc[0][0], Ah[0][kb][0], Ah[0][kb][1], bh0);
                mma1688(acc[0][1], Ah[1][kb][0], Ah[1][kb][1], bh0);
                mma1688(acc[1][0], Ah[0][kb][0], Ah[0][kb][1], bh1);
                mma1688(acc[1][1], Ah[1][kb][0], Ah[1][kb][1], bh1);
                mma1688(acc[2][0], Ah[0][kb][0], Ah[0][kb][1], bh2);
                mma1688(acc[2][1], Ah[1][kb][0], Ah[1][kb][1], bh2);
                mma1688(acc[3][0], Ah[0][kb][0], Ah[0][kb][1], bh3);
                mma1688(acc[3][1], Ah[1][kb][0], Ah[1][kb][1], bh3);
                // term lo*hi
                mma1688(acc[0][0], Al[0][kb][0], Al[0][kb][1], bh0);
                mma1688(acc[0][1], Al[1][kb][0], Al[1][kb][1], bh0);
                mma1688(acc[1][0], Al[0][kb][0], Al[0][kb][1], bh1);
                mma1688(acc[1][1], Al[1][kb][0], Al[1][kb][1], bh1);
                mma1688(acc[2][0], Al[0][kb][0], Al[0][kb][1], bh2);
                mma1688(acc[2][1], Al[1][kb][0], Al[1][kb][1], bh2);
                mma1688(acc[3][0], Al[0][kb][0], Al[0][kb][1], bh3);
                mma1688(acc[3][1], Al[1][kb][0], Al[1][kb][1], bh3);
                // term hi*lo
                mma1688(acc[0][0], Ah[0][kb][0], Ah[0][kb][1], bl0);
                mma1688(acc[0][1], Ah[1][kb][0], Ah[1][kb][1], bl0);
                mma1688(acc[1][0], Ah[0][kb][0], Ah[0][kb][1], bl1);
                mma1688(acc[1][1], Ah[1][kb][0], Ah[1][kb][1], bl1);
                mma1688(acc[2][0], Ah[0][kb][0], Ah[0][kb][1], bl2);
                mma1688(acc[2][1], Ah[1][kb][0], Ah[1][kb][1], bl2);
                mma1688(acc[3][0], Ah[0][kb][0], Ah[0][kb][1], bl3);
                mma1688(acc[3][1], Ah[1][kb][0], Ah[1][kb][1], bl3);
            }

            // Argmin update (ascending n, strict '<' = first-min, jnp.argmin).
            #pragma unroll
            for (int cb = 0; cb < 4; ++cb) {
                int n0 = nch * CH + cb * 8 + m * 2;
                #pragma unroll
                for (int t = 0; t < 2; ++t) {
                    int s0 = t * 2, s1 = t * 2 + 1;   // rows g, g+8 (per tile)
                    float4 a = acc[cb][t];
                    if (a.x < best[s0]) { best[s0] = a.x; bidx[s0] = n0; }
                    if (a.y < best[s0]) { best[s0] = a.y; bidx[s0] = n0 + 1; }
                    if (a.z < best[s1]) { best[s1] = a.z; bidx[s1] = n0; }
                    if (a.w < best[s1]) { best[s1] = a.w; bidx[s1] = n0 + 1; }
                }
            }
        }
    }

    // Reduce across the 4 lanes (m) sharing each row; tie -> smaller index.
    #pragma unroll
    for (int s = 0; s < 4; ++s) {
        #pragma unroll
        for (int o = 1; o <= 2; o <<= 1) {
            float ob = __shfl_xor_sync(0xFFFFFFFFu, best[s], o);
            int   oi = __shfl_xor_sync(0xFFFFFFFFu, bidx[s], o);
            if (ob < best[s] || (ob == best[s] && oi < bidx[s])) {
                best[s] = ob; bidx[s] = oi;
            }
        }
    }
    if (m == 0) {
        int* si = (int*)(sm + IDX_F);
        si[wb + g]          = bidx[0];
        si[wb + g + 8]      = bidx[1];
        si[wb + 16 + g]     = bidx[2];
        si[wb + 16 + g + 8] = bidx[3];
    }
    __syncthreads();

    // Cooperative one-hot: 128 rows x 128 quads, coalesced STG.128.
    const int* si = (const int*)(sm + IDX_F);
    float4* ob4 = (float4*)(out + (size_t)rowbase * Sq);
    #pragma unroll 4
    for (int it = 0; it < 128; ++it) {
        int idx = it * NTHR + tid;
        int r = idx >> 7, c4 = idx & 127;
        int b = si[r];
        int base = c4 << 2;
        float4 v;
        v.x = (b == base)     ? 1.0f : 0.0f;
        v.y = (b == base + 1) ? 1.0f : 0.0f;
        v.z = (b == base + 2) ? 1.0f : 0.0f;
        v.w = (b == base + 3) ? 1.0f : 0.0f;
        ob4[idx] = v;
    }
}

// ---------------------------------------------------------------------------
extern "C" void kernel_launch(void* const* d_in, const int* in_sizes, int n_in,
                              void* d_out, int out_size) {
    const float* x       = (const float*)d_in[0];
    const float* c_sum   = (const float*)d_in[1];
    const float* c_count = (const float*)d_in[2];
    float* out   = (float*)d_out;
    float* out_c = out + ONEHOT_ELEMS;

    (void)in_sizes; (void)n_in; (void)out_size;

    cudaFuncSetAttribute(vq_kernel,
                         cudaFuncAttributeMaxDynamicSharedMemorySize,
                         SMEM_TOTAL);

    prep_kernel<<<Hq * Sq, 32>>>(c_sum, c_count, out_c);
    vq_kernel<<<(Bq * Hq * Lq) / ROWS, NTHR, SMEM_TOTAL>>>(x, out);
}

// round 12
// speedup vs baseline: 1.1863x; 1.1301x over previous
#include <cuda_runtime.h>
#include <cstdint>

// Quantizer — VQ assignment via mma.sync tf32 3-term split (sm_100-safe PTX).
//   x [B,H,L,D] f32, c_sum [H,S,D] f32, c_count [H,S] f32
//   out = [delta_onehot [B,H,L,S] f32 | c [H,S,D] f32]
// score_s = |c_s|^2 + x.(-2 c_s); 3-term tf32 split, fp32 accumulate
// (residual ~1e-5 << argmin gaps; rel_err measured 0.0 R7-R11).
// R12 = R9 compute core + cp.async.bulk producer/consumer mbarrier ring:
// per-chunk copy-issue (64 LDGSTS x 8cyc per warp) and ALL mainloop
// __syncthreads removed. Codebook stored pre-padded so one bulk copy
// moves a whole 17408B chunk. 4 slots; slots 2,3 reuse dead A-staging smem.

#define Bq 4
#define Hq 16
#define Lq 4096
#define Dq 64
#define Sq 512
#define ONEHOT_ELEMS ((size_t)Bq * Hq * Lq * Sq)

#define ROWS 128
#define NTHR 128
#define CH   32
#define RSTRIDE 136                        // padded row (floats)
#define SLOT_F  (CH * RSTRIDE)             // 4352 floats = 17408 B per chunk
#define CHUNK_BYTES (SLOT_F * 4)
#define NCHUNK  (Sq / CH)                  // 16

// Codebook scratch, PRE-PADDED chunk layout: per (h,chunk): 32 rows x
// [hi 64 | lo 64 | pad 8] floats, rows k-permuted for mma B fragments.
__device__ float g_cbB[Hq * NCHUNK * SLOT_F];   // ~4.5 MB
__device__ float g_c2[Hq * Sq];                 // 32 KB

// -------------------- helpers --------------------
__device__ __forceinline__ uint32_t smem_u32(const void* p) {
    uint32_t a;
    asm("{ .reg .u64 t; cvta.to.shared.u64 t, %1; cvt.u32.u64 %0, t; }"
        : "=r"(a) : "l"(p));
    return a;
}
__device__ __forceinline__ float to_tf32(float x) {
    uint32_t u;
    asm("cvt.rna.tf32.f32 %0, %1;" : "=r"(u) : "f"(x));
    return __uint_as_float(u);
}

#define MBAR_INIT(a, n) \
    asm volatile("mbarrier.init.shared.b64 [%0], %1;" :: "r"(a), "r"(n) : "memory")
#define MBAR_EXPECT_TX(a, tx) \
    asm volatile("mbarrier.arrive.expect_tx.shared.b64 _, [%0], %1;" \
                 :: "r"(a), "r"(tx) : "memory")
#define MBAR_ARRIVE(a) \
    asm volatile("mbarrier.arrive.shared.b64 _, [%0];" :: "r"(a) : "memory")
#define MBAR_WAIT(a, ph) do {                                              \
    uint32_t _m = (a), _p = (ph), _d;                                      \
    asm volatile("{\n\t.reg .pred p;\n\t"                                  \
        "mbarrier.try_wait.parity.acquire.cta.shared::cta.b64 p, [%1], %2;\n\t" \
        "selp.b32 %0, 1, 0, p;\n\t}" : "=r"(_d) : "r"(_m), "r"(_p) : "memory"); \
    if (!_d) {                                                             \
        asm volatile("{\n\t.reg .pred P1;\n\tWL%=:\n\t"                    \
            "mbarrier.try_wait.parity.acquire.cta.shared::cta.b64 P1, [%0], %1, 0x989680;\n\t" \
            "@P1 bra.uni WD%=;\n\tbra.uni WL%=;\n\tWD%=:\n\t}"             \
            :: "r"(_m), "r"(_p) : "memory");                               \
    }                                                                      \
} while (0)

__device__ __forceinline__ void bulk_cp(uint32_t dst, const void* src,
                                        uint32_t bytes, uint32_t mbar) {
    asm volatile(
        "cp.async.bulk.shared::cta.global.mbarrier::complete_tx::bytes "
        "[%0], [%1], %2, [%3];"
        :: "r"(dst), "l"(src), "r"(bytes), "r"(mbar) : "memory");
}

// m16n8k8 tf32 row.col; operand mapping verified R6-R11 (rel_err 0.0).
__device__ __forceinline__ void mma1688(float4& d, float2 a0, float2 a1, float2 b) {
    asm("mma.sync.aligned.m16n8k8.row.col.f32.tf32.tf32.f32 "
        "{%0,%1,%2,%3}, {%4,%5,%6,%7}, {%8,%9}, {%0,%1,%2,%3};"
        : "+f"(d.x), "+f"(d.y), "+f"(d.z), "+f"(d.w)
        : "r"(__float_as_uint(a0.x)), "r"(__float_as_uint(a1.x)),
          "r"(__float_as_uint(a0.y)), "r"(__float_as_uint(a1.y)),
          "r"(__float_as_uint(b.x)),  "r"(__float_as_uint(b.y)));
}

// k-permutation: pos(k) puts (m, m+4) adjacent within each 8-block.
__device__ __forceinline__ int kpos(int k) {
    return (k & ~7) + ((k & 3) << 1) + ((k >> 2) & 1);
}

// -------------------- prep --------------------
__global__ void prep_kernel(const float* __restrict__ c_sum,
                            const float* __restrict__ c_count,
                            float* __restrict__ out_c) {
    const int cw = blockIdx.x;            // h*S + s
    const int lane = threadIdx.x;         // 2 dims per lane
    const int h = cw >> 9, s = cw & 511;
    float cnt = fmaxf(c_count[cw], 1e-6f);

    float2 v = ((const float2*)(c_sum + (size_t)cw * Dq))[lane];
    float a = v.x / cnt;                  // IEEE divide: matches reference
    float b = v.y / cnt;
    ((float2*)(out_c + (size_t)cw * Dq))[lane] = make_float2(a, b);

    // Pre-padded chunk layout: chunk = s>>5, row-in-chunk = s&31.
    float* row = g_cbB + ((size_t)(h * NCHUNK + (s >> 5)) * SLOT_F)
                       + (size_t)(s & 31) * RSTRIDE;
    int k0 = 2 * lane, k1 = 2 * lane + 1;
    float m0 = -2.0f * a, m1 = -2.0f * b;
    float h0 = to_tf32(m0), h1 = to_tf32(m1);
    row[kpos(k0)]      = h0;
    row[kpos(k1)]      = h1;
    row[64 + kpos(k0)] = to_tf32(m0 - h0);
    row[64 + kpos(k1)] = to_tf32(m1 - h1);

    float sq = a * a + b * b;
    #pragma unroll
    for (int o = 16; o > 0; o >>= 1) sq += __shfl_xor_sync(0xFFFFFFFFu, sq, o);
    if (lane == 0) g_c2[cw] = sq;
}

// -------------------- main --------------------
// CTA: 128 threads (4 warps), 128 rows, 2 CTAs/SM. Warp tile M=32, A hi/lo in
// registers. B: 4-slot ring (slots 2,3 in dead A region), bulk-copy filled,
// mbarrier producer/consumer; NO syncthreads in the mainloop.
#define AREG_F  (ROWS * RSTRIDE)      // 17408 floats (holds slots 2,3)
#define B0_F    AREG_F                // slot 0: 17408
#define B1_F    (B0_F + SLOT_F)      // slot 1: 21760
#define C2_F    (B1_F + SLOT_F)      // 26112
#define IDX_F   (C2_F + Sq)          // 26624
#define MBAR_F  (IDX_F + ROWS)       // 26752 (16B-aligned: 26752*4)
#define SMEM_TOTAL (MBAR_F * 4 + 64)

__global__ __launch_bounds__(NTHR, 2)
void vq_kernel(const float* __restrict__ x, float* __restrict__ out) {
    extern __shared__ float sm[];
    const uint32_t sb = smem_u32(sm);
    const int tid = threadIdx.x;
    const int wid = tid >> 5, lane = tid & 31;
    const int g = lane >> 2, m = lane & 3;
    const int wb = wid * 32;

    const int rowbase = blockIdx.x * ROWS;
    const int h = (blockIdx.x >> 5) & (Hq - 1);   // 32 CTAs per (b,h)
    const char* cbb = (const char*)(g_cbB + (size_t)h * NCHUNK * SLOT_F);

    const uint32_t slot_f[4] = {B0_F, B1_F, 0u, SLOT_F};
    const uint32_t mb_full  = sb + MBAR_F * 4;         // 4 x 8B
    const uint32_t mb_empty = mb_full + 32;            // 4 x 8B

    if (tid == 0) {
        #pragma unroll
        for (int i = 0; i < 4; ++i) {
            MBAR_INIT(mb_full + 8 * i, 1);
            MBAR_INIT(mb_empty + 8 * i, 4);
        }
    }
    __syncthreads();                       // barrier init visible

    // Producer prologue: chunks 0,1 -> slots 0,1 (disjoint from A region).
    if (tid == 0) {
        MBAR_EXPECT_TX(mb_full + 0, CHUNK_BYTES);
        bulk_cp(sb + B0_F * 4, cbb, CHUNK_BYTES, mb_full + 0);
        MBAR_EXPECT_TX(mb_full + 8, CHUNK_BYTES);
        bulk_cp(sb + B1_F * 4, cbb + CHUNK_BYTES, CHUNK_BYTES, mb_full + 8);
    }

    // Stage c2 + A tile (hi/lo tf32, k-permuted, padded rows).
    for (int i = tid; i < Sq; i += NTHR) sm[C2_F + i] = g_c2[h * Sq + i];
    {
        const float4* xb = (const float4*)(x + (size_t)rowbase * Dq);
        #pragma unroll
        for (int it = 0; it < 8; ++it) {
            int i = it * NTHR + tid;          // 128 rows x 8 kblocks
            int r = i >> 3, kb = i & 7;
            float4 v0 = xb[r * 16 + kb * 2];
            float4 v1 = xb[r * 16 + kb * 2 + 1];
            float h0 = to_tf32(v0.x), h1 = to_tf32(v0.y),
                  h2 = to_tf32(v0.z), h3 = to_tf32(v0.w),
                  h4 = to_tf32(v1.x), h5 = to_tf32(v1.y),
                  h6 = to_tf32(v1.z), h7 = to_tf32(v1.w);
            float l0 = to_tf32(v0.x - h0), l1 = to_tf32(v0.y - h1),
                  l2 = to_tf32(v0.z - h2), l3 = to_tf32(v0.w - h3),
                  l4 = to_tf32(v1.x - h4), l5 = to_tf32(v1.y - h5),
                  l6 = to_tf32(v1.z - h6), l7 = to_tf32(v1.w - h7);
            float* dh = sm + r * RSTRIDE + kb * 8;
            ((float4*)dh)[0] = make_float4(h0, h4, h1, h5);
            ((float4*)dh)[1] = make_float4(h2, h6, h3, h7);
            float* dl = dh + 64;
            ((float4*)dl)[0] = make_float4(l0, l4, l1, l5);
            ((float4*)dl)[1] = make_float4(l2, l6, l3, l7);
        }
    }
    __syncthreads();

    // A fragments to registers: [tile][kblock][row-half], hi and lo.
    float2 Ah[2][8][2], Al[2][8][2];
    #pragma unroll
    for (int t = 0; t < 2; ++t)
        #pragma unroll
        for (int kb = 0; kb < 8; ++kb) {
            int r0 = wb + t * 16 + g;
            const float* b0 = sm + r0 * RSTRIDE + kb * 8 + m * 2;
            const float* b8 = b0 + 8 * RSTRIDE;
            Ah[t][kb][0] = *(const float2*)b0;
            Ah[t][kb][1] = *(const float2*)b8;
            Al[t][kb][0] = *(const float2*)(b0 + 64);
            Al[t][kb][1] = *(const float2*)(b8 + 64);
        }
    __syncthreads();   // A region dead -> slots 2,3 may be filled

    if (tid == 0) {
        MBAR_EXPECT_TX(mb_full + 16, CHUNK_BYTES);
        bulk_cp(sb + 0, cbb + 2 * (size_t)CHUNK_BYTES, CHUNK_BYTES, mb_full + 16);
        MBAR_EXPECT_TX(mb_full + 24, CHUNK_BYTES);
        bulk_cp(sb + SLOT_F * 4, cbb + 3 * (size_t)CHUNK_BYTES, CHUNK_BYTES,
                mb_full + 24);
    }

    float best[4] = {3.0e38f, 3.0e38f, 3.0e38f, 3.0e38f};
    int bidx[4] = {0, 0, 0, 0};

    // Mainloop: no __syncthreads. Each warp: wait full -> compute -> arrive
    // empty. tid0 refills a slot only after all 4 warps arrived on it.
    for (int p = 0; p < NCHUNK; ++p) {
        const int s = p & 3;
        const uint32_t ph = (uint32_t)((p >> 2) & 1);
        MBAR_WAIT(mb_full + 8 * s, ph);

        const float* Bbuf = sm + slot_f[s];

        float4 acc[4][2];                 // [colblock][tile] -> 8 chains
        #pragma unroll
        for (int cb = 0; cb < 4; ++cb) {
            float2 cv = *(const float2*)(sm + C2_F + p * CH + cb * 8 + m * 2);
            #pragma unroll
            for (int t = 0; t < 2; ++t)
                acc[cb][t] = make_float4(cv.x, cv.y, cv.x, cv.y);
        }

        const float* bn0 = Bbuf + g * RSTRIDE + m * 2;
        const float* bn1 = bn0 + 8 * RSTRIDE;
        const float* bn2 = bn0 + 16 * RSTRIDE;
        const float* bn3 = bn0 + 24 * RSTRIDE;
        #pragma unroll
        for (int kb = 0; kb < 8; ++kb) {
            float2 bh0 = *(const float2*)(bn0 + kb * 8);
            float2 bh1 = *(const float2*)(bn1 + kb * 8);
            float2 bh2 = *(const float2*)(bn2 + kb * 8);
            float2 bh3 = *(const float2*)(bn3 + kb * 8);
            float2 bl0 = *(const float2*)(bn0 + 64 + kb * 8);
            float2 bl1 = *(const float2*)(bn1 + 64 + kb * 8);
            float2 bl2 = *(const float2*)(bn2 + 64 + kb * 8);
            float2 bl3 = *(const float2*)(bn3 + 64 + kb * 8);
            // term hi*hi
            mma1688(acc[0][0], Ah[0][kb][0], Ah[0][kb][1], bh0);
            mma1688(acc[0][1], Ah[1][kb][0], Ah[1][kb][1], bh0);
            mma1688(acc[1][0], Ah[0][kb][0], Ah[0][kb][1], bh1);
            mma1688(acc[1][1], Ah[1][kb][0], Ah[1][kb][1], bh1);
            mma1688(acc[2][0], Ah[0][kb][0], Ah[0][kb][1], bh2);
            mma1688(acc[2][1], Ah[1][kb][0], Ah[1][kb][1], bh2);
            mma1688(acc[3][0], Ah[0][kb][0], Ah[0][kb][1], bh3);
            mma1688(acc[3][1], Ah[1][kb][0], Ah[1][kb][1], bh3);
            // term lo*hi
            mma1688(acc[0][0], Al[0][kb][0], Al[0][kb][1], bh0);
            mma1688(acc[0][1], Al[1][kb][0], Al[1][kb][1], bh0);
            mma1688(acc[1][0], Al[0][kb][0], Al[0][kb][1], bh1);
            mma1688(acc[1][1], Al[1][kb][0], Al[1][kb][1], bh1);
            mma1688(acc[2][0], Al[0][kb][0], Al[0][kb][1], bh2);
            mma1688(acc[2][1], Al[1][kb][0], Al[1][kb][1], bh2);
            mma1688(acc[3][0], Al[0][kb][0], Al[0][kb][1], bh3);
            mma1688(acc[3][1], Al[1][kb][0], Al[1][kb][1], bh3);
            // term hi*lo
            mma1688(acc[0][0], Ah[0][kb][0], Ah[0][kb][1], bl0);
            mma1688(acc[0][1], Ah[1][kb][0], Ah[1][kb][1], bl0);
            mma1688(acc[1][0], Ah[0][kb][0], Ah[0][kb][1], bl1);
            mma1688(acc[1][1], Ah[1][kb][0], Ah[1][kb][1], bl1);
            mma1688(acc[2][0], Ah[0][kb][0], Ah[0][kb][1], bl2);
            mma1688(acc[2][1], Ah[1][kb][0], Ah[1][kb][1], bl2);
            mma1688(acc[3][0], Ah[0][kb][0], Ah[0][kb][1], bl3);
            mma1688(acc[3][1], Ah[1][kb][0], Ah[1][kb][1], bl3);
        }

        // Argmin update (ascending n, strict '<' = first-min, jnp.argmin).
        #pragma unroll
        for (int cb = 0; cb < 4; ++cb) {
            int n0 = p * CH + cb * 8 + m * 2;
            #pragma unroll
            for (int t = 0; t < 2; ++t) {
                int s0 = t * 2, s1 = t * 2 + 1;   // rows g, g+8 (per tile)
                float4 a = acc[cb][t];
                if (a.x < best[s0]) { best[s0] = a.x; bidx[s0] = n0; }
                if (a.y < best[s0]) { best[s0] = a.y; bidx[s0] = n0 + 1; }
                if (a.z < best[s1]) { best[s1] = a.z; bidx[s1] = n0; }
                if (a.w < best[s1]) { best[s1] = a.w; bidx[s1] = n0 + 1; }
            }
        }

        __syncwarp();                     // all lanes done reading the slot
        if (lane == 0) MBAR_ARRIVE(mb_empty + 8 * s);
        if (tid == 0 && p + 4 < NCHUNK) { // refill this slot with chunk p+4
            MBAR_WAIT(mb_empty + 8 * s, ph);
            MBAR_EXPECT_TX(mb_full + 8 * s, CHUNK_BYTES);
            bulk_cp(sb + slot_f[s] * 4, cbb + (size_t)(p + 4) * CHUNK_BYTES,
                    CHUNK_BYTES, mb_full + 8 * s);
        }
    }

    // Reduce across the 4 lanes (m) sharing each row; tie -> smaller index.
    #pragma unroll
    for (int s = 0; s < 4; ++s) {
        #pragma unroll
        for (int o = 1; o <= 2; o <<= 1) {
            float ob = __shfl_xor_sync(0xFFFFFFFFu, best[s], o);
            int   oi = __shfl_xor_sync(0xFFFFFFFFu, bidx[s], o);
            if (ob < best[s] || (ob == best[s] && oi < bidx[s])) {
                best[s] = ob; bidx[s] = oi;
            }
        }
    }
    if (m == 0) {
        int* si = (int*)(sm + IDX_F);
        si[wb + g]          = bidx[0];
        si[wb + g + 8]      = bidx[1];
        si[wb + 16 + g]     = bidx[2];
        si[wb + 16 + g + 8] = bidx[3];
    }
    __syncthreads();

    // Cooperative one-hot: 128 rows x 128 quads, coalesced STG.128.
    const int* si = (const int*)(sm + IDX_F);
    float4* ob4 = (float4*)(out + (size_t)rowbase * Sq);
    #pragma unroll 4
    for (int it = 0; it < 128; ++it) {
        int idx = it * NTHR + tid;
        int r = idx >> 7, c4 = idx & 127;
        int b = si[r];
        int base = c4 << 2;
        float4 v;
        v.x = (b == base)     ? 1.0f : 0.0f;
        v.y = (b == base + 1) ? 1.0f : 0.0f;
        v.z = (b == base + 2) ? 1.0f : 0.0f;
        v.w = (b == base + 3) ? 1.0f : 0.0f;
        ob4[idx] = v;
    }
}

// ---------------------------------------------------------------------------
extern "C" void kernel_launch(void* const* d_in, const int* in_sizes, int n_in,
                              void* d_out, int out_size) {
    const float* x       = (const float*)d_in[0];
    const float* c_sum   = (const float*)d_in[1];
    const float* c_count = (const float*)d_in[2];
    float* out   = (float*)d_out;
    float* out_c = out + ONEHOT_ELEMS;

    (void)in_sizes; (void)n_in; (void)out_size;

    cudaFuncSetAttribute(vq_kernel,
                         cudaFuncAttributeMaxDynamicSharedMemorySize,
                         SMEM_TOTAL);

    prep_kernel<<<Hq * Sq, 32>>>(c_sum, c_count, out_c);
    vq_kernel<<<(Bq * Hq * Lq) / ROWS, NTHR, SMEM_TOTAL>>>(x, out);
}

// round 14
// speedup vs baseline: 1.2754x; 1.0751x over previous
#include <cuda_runtime.h>
#include <cstdint>

// Quantizer — VQ assignment via mma.sync tf32 3-term split (sm_100-safe PTX).
//   x [B,H,L,D] f32, c_sum [H,S,D] f32, c_count [H,S] f32
//   out = [delta_onehot [B,H,L,S] f32 | c [H,S,D] f32]
// score_s = |c_s|^2 + x.(-2 c_s); 3-term tf32 split, fp32 accumulate
// (residual ~1e-5 << argmin gaps; rel_err 0.0 R7-R12).
// R12 -> R13: (1) one-hot ZEROS written inside the mainloop (1/16 per chunk,
// hides under MMA shadow; final epilogue = 128 scattered 1.0f stores);
// (2) accumulators zero-init, c2 added at argmin time (kills the per-chunk
// LDS->MMA cold-start chain). Ring/copy machinery unchanged from R12.
// (R13 bench was an infra flake; resubmitting unchanged.)

#define Bq 4
#define Hq 16
#define Lq 4096
#define Dq 64
#define Sq 512
#define ONEHOT_ELEMS ((size_t)Bq * Hq * Lq * Sq)

#define ROWS 128
#define NTHR 128
#define CH   32
#define RSTRIDE 136                        // padded row (floats)
#define SLOT_F  (CH * RSTRIDE)             // 4352 floats = 17408 B per chunk
#define CHUNK_BYTES (SLOT_F * 4)
#define NCHUNK  (Sq / CH)                  // 16

// Codebook scratch, PRE-PADDED chunk layout: per (h,chunk): 32 rows x
// [hi 64 | lo 64 | pad 8] floats, rows k-permuted for mma B fragments.
__device__ float g_cbB[Hq * NCHUNK * SLOT_F];   // ~4.5 MB
__device__ float g_c2[Hq * Sq];                 // 32 KB

// -------------------- helpers --------------------
__device__ __forceinline__ uint32_t smem_u32(const void* p) {
    uint32_t a;
    asm("{ .reg .u64 t; cvta.to.shared.u64 t, %1; cvt.u32.u64 %0, t; }"
        : "=r"(a) : "l"(p));
    return a;
}
__device__ __forceinline__ float to_tf32(float x) {
    uint32_t u;
    asm("cvt.rna.tf32.f32 %0, %1;" : "=r"(u) : "f"(x));
    return __uint_as_float(u);
}

#define MBAR_INIT(a, n) \
    asm volatile("mbarrier.init.shared.b64 [%0], %1;" :: "r"(a), "r"(n) : "memory")
#define MBAR_EXPECT_TX(a, tx) \
    asm volatile("mbarrier.arrive.expect_tx.shared.b64 _, [%0], %1;" \
                 :: "r"(a), "r"(tx) : "memory")
#define MBAR_ARRIVE(a) \
    asm volatile("mbarrier.arrive.shared.b64 _, [%0];" :: "r"(a) : "memory")
#define MBAR_WAIT(a, ph) do {                                              \
    uint32_t _m = (a), _p = (ph), _d;                                      \
    asm volatile("{\n\t.reg .pred p;\n\t"                                  \
        "mbarrier.try_wait.parity.acquire.cta.shared::cta.b64 p, [%1], %2;\n\t" \
        "selp.b32 %0, 1, 0, p;\n\t}" : "=r"(_d) : "r"(_m), "r"(_p) : "memory"); \
    if (!_d) {                                                             \
        asm volatile("{\n\t.reg .pred P1;\n\tWL%=:\n\t"                    \
            "mbarrier.try_wait.parity.acquire.cta.shared::cta.b64 P1, [%0], %1, 0x989680;\n\t" \
            "@P1 bra.uni WD%=;\n\tbra.uni WL%=;\n\tWD%=:\n\t}"             \
            :: "r"(_m), "r"(_p) : "memory");                               \
    }                                                                      \
} while (0)

__device__ __forceinline__ void bulk_cp(uint32_t dst, const void* src,
                                        uint32_t bytes, uint32_t mbar) {
    asm volatile(
        "cp.async.bulk.shared::cta.global.mbarrier::complete_tx::bytes "
        "[%0], [%1], %2, [%3];"
        :: "r"(dst), "l"(src), "r"(bytes), "r"(mbar) : "memory");
}

// m16n8k8 tf32 row.col; operand mapping verified R6-R12 (rel_err 0.0).
__device__ __forceinline__ void mma1688(float4& d, float2 a0, float2 a1, float2 b) {
    asm("mma.sync.aligned.m16n8k8.row.col.f32.tf32.tf32.f32 "
        "{%0,%1,%2,%3}, {%4,%5,%6,%7}, {%8,%9}, {%0,%1,%2,%3};"
        : "+f"(d.x), "+f"(d.y), "+f"(d.z), "+f"(d.w)
        : "r"(__float_as_uint(a0.x)), "r"(__float_as_uint(a1.x)),
          "r"(__float_as_uint(a0.y)), "r"(__float_as_uint(a1.y)),
          "r"(__float_as_uint(b.x)),  "r"(__float_as_uint(b.y)));
}

// k-permutation: pos(k) puts (m, m+4) adjacent within each 8-block.
__device__ __forceinline__ int kpos(int k) {
    return (k & ~7) + ((k & 3) << 1) + ((k >> 2) & 1);
}

// -------------------- prep --------------------
__global__ void prep_kernel(const float* __restrict__ c_sum,
                            const float* __restrict__ c_count,
                            float* __restrict__ out_c) {
    const int cw = blockIdx.x;            // h*S + s
    const int lane = threadIdx.x;         // 2 dims per lane
    const int h = cw >> 9, s = cw & 511;
    float cnt = fmaxf(c_count[cw], 1e-6f);

    float2 v = ((const float2*)(c_sum + (size_t)cw * Dq))[lane];
    float a = v.x / cnt;                  // IEEE divide: matches reference
    float b = v.y / cnt;
    ((float2*)(out_c + (size_t)cw * Dq))[lane] = make_float2(a, b);

    // Pre-padded chunk layout: chunk = s>>5, row-in-chunk = s&31.
    float* row = g_cbB + ((size_t)(h * NCHUNK + (s >> 5)) * SLOT_F)
                       + (size_t)(s & 31) * RSTRIDE;
    int k0 = 2 * lane, k1 = 2 * lane + 1;
    float m0 = -2.0f * a, m1 = -2.0f * b;
    float h0 = to_tf32(m0), h1 = to_tf32(m1);
    row[kpos(k0)]      = h0;
    row[kpos(k1)]      = h1;
    row[64 + kpos(k0)] = to_tf32(m0 - h0);
    row[64 + kpos(k1)] = to_tf32(m1 - h1);

    float sq = a * a + b * b;
    #pragma unroll
    for (int o = 16; o > 0; o >>= 1) sq += __shfl_xor_sync(0xFFFFFFFFu, sq, o);
    if (lane == 0) g_c2[cw] = sq;
}

// -------------------- main --------------------
// CTA: 128 threads (4 warps), 128 rows, 2 CTAs/SM. Warp tile M=32, A hi/lo in
// registers. B: 4-slot ring (slots 2,3 in dead A region), bulk-copy filled,
// mbarrier producer/consumer; NO syncthreads in the mainloop.
#define AREG_F  (ROWS * RSTRIDE)      // 17408 floats (holds slots 2,3)
#define B0_F    AREG_F                // slot 0: 17408
#define B1_F    (B0_F + SLOT_F)      // slot 1: 21760
#define C2_F    (B1_F + SLOT_F)      // 26112
#define IDX_F   (C2_F + Sq)          // 26624
#define MBAR_F  (IDX_F + ROWS)       // 26752 (16B-aligned: 26752*4)
#define SMEM_TOTAL (MBAR_F * 4 + 64)

__global__ __launch_bounds__(NTHR, 2)
void vq_kernel(const float* __restrict__ x, float* __restrict__ out) {
    extern __shared__ float sm[];
    const uint32_t sb = smem_u32(sm);
    const int tid = threadIdx.x;
    const int wid = tid >> 5, lane = tid & 31;
    const int g = lane >> 2, m = lane & 3;
    const int wb = wid * 32;

    const int rowbase = blockIdx.x * ROWS;
    const int h = (blockIdx.x >> 5) & (Hq - 1);   // 32 CTAs per (b,h)
    const char* cbb = (const char*)(g_cbB + (size_t)h * NCHUNK * SLOT_F);

    const uint32_t slot_f[4] = {B0_F, B1_F, 0u, SLOT_F};
    const uint32_t mb_full  = sb + MBAR_F * 4;         // 4 x 8B
    const uint32_t mb_empty = mb_full + 32;            // 4 x 8B

    if (tid == 0) {
        #pragma unroll
        for (int i = 0; i < 4; ++i) {
            MBAR_INIT(mb_full + 8 * i, 1);
            MBAR_INIT(mb_empty + 8 * i, 4);
        }
    }
    __syncthreads();                       // barrier init visible

    // Producer prologue: chunks 0,1 -> slots 0,1 (disjoint from A region).
    if (tid == 0) {
        MBAR_EXPECT_TX(mb_full + 0, CHUNK_BYTES);
        bulk_cp(sb + B0_F * 4, cbb, CHUNK_BYTES, mb_full + 0);
        MBAR_EXPECT_TX(mb_full + 8, CHUNK_BYTES);
        bulk_cp(sb + B1_F * 4, cbb + CHUNK_BYTES, CHUNK_BYTES, mb_full + 8);
    }

    // Stage c2 + A tile (hi/lo tf32, k-permuted, padded rows).
    for (int i = tid; i < Sq; i += NTHR) sm[C2_F + i] = g_c2[h * Sq + i];
    {
        const float4* xb = (const float4*)(x + (size_t)rowbase * Dq);
        #pragma unroll
        for (int it = 0; it < 8; ++it) {
            int i = it * NTHR + tid;          // 128 rows x 8 kblocks
            int r = i >> 3, kb = i & 7;
            float4 v0 = xb[r * 16 + kb * 2];
            float4 v1 = xb[r * 16 + kb * 2 + 1];
            float h0 = to_tf32(v0.x), h1 = to_tf32(v0.y),
                  h2 = to_tf32(v0.z), h3 = to_tf32(v0.w),
                  h4 = to_tf32(v1.x), h5 = to_tf32(v1.y),
                  h6 = to_tf32(v1.z), h7 = to_tf32(v1.w);
            float l0 = to_tf32(v0.x - h0), l1 = to_tf32(v0.y - h1),
                  l2 = to_tf32(v0.z - h2), l3 = to_tf32(v0.w - h3),
                  l4 = to_tf32(v1.x - h4), l5 = to_tf32(v1.y - h5),
                  l6 = to_tf32(v1.z - h6), l7 = to_tf32(v1.w - h7);
            float* dh = sm + r * RSTRIDE + kb * 8;
            ((float4*)dh)[0] = make_float4(h0, h4, h1, h5);
            ((float4*)dh)[1] = make_float4(h2, h6, h3, h7);
            float* dl = dh + 64;
            ((float4*)dl)[0] = make_float4(l0, l4, l1, l5);
            ((float4*)dl)[1] = make_float4(l2, l6, l3, l7);
        }
    }
    __syncthreads();

    // A fragments to registers: [tile][kblock][row-half], hi and lo.
    float2 Ah[2][8][2], Al[2][8][2];
    #pragma unroll
    for (int t = 0; t < 2; ++t)
        #pragma unroll
        for (int kb = 0; kb < 8; ++kb) {
            int r0 = wb + t * 16 + g;
            const float* b0 = sm + r0 * RSTRIDE + kb * 8 + m * 2;
            const float* b8 = b0 + 8 * RSTRIDE;
            Ah[t][kb][0] = *(const float2*)b0;
            Ah[t][kb][1] = *(const float2*)b8;
            Al[t][kb][0] = *(const float2*)(b0 + 64);
            Al[t][kb][1] = *(const float2*)(b8 + 64);
        }
    __syncthreads();   // A region dead -> slots 2,3 may be filled

    if (tid == 0) {
        MBAR_EXPECT_TX(mb_full + 16, CHUNK_BYTES);
        bulk_cp(sb + 0, cbb + 2 * (size_t)CHUNK_BYTES, CHUNK_BYTES, mb_full + 16);
        MBAR_EXPECT_TX(mb_full + 24, CHUNK_BYTES);
        bulk_cp(sb + SLOT_F * 4, cbb + 3 * (size_t)CHUNK_BYTES, CHUNK_BYTES,
                mb_full + 24);
    }

    float best[4] = {3.0e38f, 3.0e38f, 3.0e38f, 3.0e38f};
    int bidx[4] = {0, 0, 0, 0};

    float4* zb = (float4*)(out + (size_t)rowbase * Sq);
    const float4 zero4 = make_float4(0.0f, 0.0f, 0.0f, 0.0f);

    // Mainloop: no __syncthreads. Each warp: wait full -> MMAs -> zero-fill
    // 1/16 of one-hot (store-issue hides under MMA shadow) -> argmin ->
    // arrive empty. tid0 refills a slot only after all 4 warps arrived.
    for (int p = 0; p < NCHUNK; ++p) {
        const int s = p & 3;
        const uint32_t ph = (uint32_t)((p >> 2) & 1);
        MBAR_WAIT(mb_full + 8 * s, ph);

        const float* Bbuf = sm + slot_f[s];

        float4 acc[4][2];                 // [colblock][tile] -> 8 chains
        #pragma unroll
        for (int cb = 0; cb < 4; ++cb)    // zero-init: no LDS cold start
            #pragma unroll
            for (int t = 0; t < 2; ++t)
                acc[cb][t] = zero4;

        const float* bn0 = Bbuf + g * RSTRIDE + m * 2;
        const float* bn1 = bn0 + 8 * RSTRIDE;
        const float* bn2 = bn0 + 16 * RSTRIDE;
        const float* bn3 = bn0 + 24 * RSTRIDE;
        #pragma unroll
        for (int kb = 0; kb < 8; ++kb) {
            float2 bh0 = *(const float2*)(bn0 + kb * 8);
            float2 bh1 = *(const float2*)(bn1 + kb * 8);
            float2 bh2 = *(const float2*)(bn2 + kb * 8);
            float2 bh3 = *(const float2*)(bn3 + kb * 8);
            float2 bl0 = *(const float2*)(bn0 + 64 + kb * 8);
            float2 bl1 = *(const float2*)(bn1 + 64 + kb * 8);
            float2 bl2 = *(const float2*)(bn2 + 64 + kb * 8);
            float2 bl3 = *(const float2*)(bn3 + 64 + kb * 8);
            // term hi*hi
            mma1688(acc[0][0], Ah[0][kb][0], Ah[0][kb][1], bh0);
            mma1688(acc[0][1], Ah[1][kb][0], Ah[1][kb][1], bh0);
            mma1688(acc[1][0], Ah[0][kb][0], Ah[0][kb][1], bh1);
            mma1688(acc[1][1], Ah[1][kb][0], Ah[1][kb][1], bh1);
            mma1688(acc[2][0], Ah[0][kb][0], Ah[0][kb][1], bh2);
            mma1688(acc[2][1], Ah[1][kb][0], Ah[1][kb][1], bh2);
            mma1688(acc[3][0], Ah[0][kb][0], Ah[0][kb][1], bh3);
            mma1688(acc[3][1], Ah[1][kb][0], Ah[1][kb][1], bh3);
            // term lo*hi
            mma1688(acc[0][0], Al[0][kb][0], Al[0][kb][1], bh0);
            mma1688(acc[0][1], Al[1][kb][0], Al[1][kb][1], bh0);
            mma1688(acc[1][0], Al[0][kb][0], Al[0][kb][1], bh1);
            mma1688(acc[1][1], Al[1][kb][0], Al[1][kb][1], bh1);
            mma1688(acc[2][0], Al[0][kb][0], Al[0][kb][1], bh2);
            mma1688(acc[2][1], Al[1][kb][0], Al[1][kb][1], bh2);
            mma1688(acc[3][0], Al[0][kb][0], Al[0][kb][1], bh3);
            mma1688(acc[3][1], Al[1][kb][0], Al[1][kb][1], bh3);
            // term hi*lo
            mma1688(acc[0][0], Ah[0][kb][0], Ah[0][kb][1], bl0);
            mma1688(acc[0][1], Ah[1][kb][0], Ah[1][kb][1], bl0);
            mma1688(acc[1][0], Ah[0][kb][0], Ah[0][kb][1], bl1);
            mma1688(acc[1][1], Ah[1][kb][0], Ah[1][kb][1], bl1);
            mma1688(acc[2][0], Ah[0][kb][0], Ah[0][kb][1], bl2);
            mma1688(acc[2][1], Ah[1][kb][0], Ah[1][kb][1], bl2);
            mma1688(acc[3][0], Ah[0][kb][0], Ah[0][kb][1], bl3);
            mma1688(acc[3][1], Ah[1][kb][0], Ah[1][kb][1], bl3);
        }

        // Zero-fill this chunk's 1/16 slice of the one-hot block: 8 coalesced
        // STG.128 per thread, issued while the tail MMAs drain.
        #pragma unroll
        for (int j = 0; j < 8; ++j)
            zb[p * 1024 + j * NTHR + tid] = zero4;

        // Argmin (ascending n, strict '<' = first-min, jnp.argmin);
        // c2 added here instead of acc-init.
        #pragma unroll
        for (int cb = 0; cb < 4; ++cb) {
            int n0 = p * CH + cb * 8 + m * 2;
            float2 cv = *(const float2*)(sm + C2_F + n0);
            #pragma unroll
            for (int t = 0; t < 2; ++t) {
                int s0 = t * 2, s1 = t * 2 + 1;   // rows g, g+8 (per tile)
                float4 a = acc[cb][t];
                float sx = a.x + cv.x, sy = a.y + cv.y;
                float sz = a.z + cv.x, sw = a.w + cv.y;
                if (sx < best[s0]) { best[s0] = sx; bidx[s0] = n0; }
                if (sy < best[s0]) { best[s0] = sy; bidx[s0] = n0 + 1; }
                if (sz < best[s1]) { best[s1] = sz; bidx[s1] = n0; }
                if (sw < best[s1]) { best[s1] = sw; bidx[s1] = n0 + 1; }
            }
        }

        __syncwarp();                     // all lanes done reading the slot
        if (lane == 0) MBAR_ARRIVE(mb_empty + 8 * s);
        if (tid == 0 && p + 4 < NCHUNK) { // refill this slot with chunk p+4
            MBAR_WAIT(mb_empty + 8 * s, ph);
            MBAR_EXPECT_TX(mb_full + 8 * s, CHUNK_BYTES);
            bulk_cp(sb + slot_f[s] * 4, cbb + (size_t)(p + 4) * CHUNK_BYTES,
                    CHUNK_BYTES, mb_full + 8 * s);
        }
    }

    // Reduce across the 4 lanes (m) sharing each row; tie -> smaller index.
    #pragma unroll
    for (int s = 0; s < 4; ++s) {
        #pragma unroll
        for (int o = 1; o <= 2; o <<= 1) {
            float ob = __shfl_xor_sync(0xFFFFFFFFu, best[s], o);
            int   oi = __shfl_xor_sync(0xFFFFFFFFu, bidx[s], o);
            if (ob < best[s] || (ob == best[s] && oi < bidx[s])) {
                best[s] = ob; bidx[s] = oi;
            }
        }
    }
    if (m == 0) {
        int* si = (int*)(sm + IDX_F);
        si[wb + g]          = bidx[0];
        si[wb + g + 8]      = bidx[1];
        si[wb + 16 + g]     = bidx[2];
        si[wb + 16 + g + 8] = bidx[3];
    }
    __syncthreads();

    // Final epilogue: one 4-byte 1.0f store per row (zeros already written;
    // __syncthreads orders them against these same-CTA stores).
    {
        const int* si = (const int*)(sm + IDX_F);
        out[(size_t)(rowbase + tid) * Sq + si[tid]] = 1.0f;
    }
}

// ---------------------------------------------------------------------------
extern "C" void kernel_launch(void* const* d_in, const int* in_sizes, int n_in,
                              void* d_out, int out_size) {
    const float* x       = (const float*)d_in[0];
    const float* c_sum   = (const float*)d_in[1];
    const float* c_count = (const float*)d_in[2];
    float* out   = (float*)d_out;
    float* out_c = out + ONEHOT_ELEMS;

    (void)in_sizes; (void)n_in; (void)out_size;

    cudaFuncSetAttribute(vq_kernel,
                         cudaFuncAttributeMaxDynamicSharedMemorySize,
                         SMEM_TOTAL);

    prep_kernel<<<Hq * Sq, 32>>>(c_sum, c_count, out_c);
    vq_kernel<<<(Bq * Hq * Lq) / ROWS, NTHR, SMEM_TOTAL>>>(x, out);
}